// round 2
// baseline (speedup 1.0000x reference)
#include <cuda_runtime.h>

// Problem constants
#define CIN     512
#define COUT    512
#define LIN     4096
#define KT      7
#define OUTL    4090
#define BATCH   4

// Tiling
#define BM      128
#define BN      128
#define BK      32
#define TW      136           // x t-window per o-tile (128 + 7 + pad)
#define WS_STRIDE 36          // 32 + 4 pad -> conflict-free A-frag reads
#define SP_STRIDE 132         // 128 + 4 pad -> conflict-free B-frag reads

// Scratch (no allocations allowed -> __device__ globals)
__device__ float g_w2[(size_t)KT * COUT * CIN];          // [k][d][c], tf32-rounded
__device__ float g_g0[(size_t)BATCH * 4096 * KT];
__device__ float g_g1[(size_t)BATCH * 4096 * KT];
__device__ int   g_j0[(size_t)BATCH * 4096 * KT];

__device__ __forceinline__ float to_tf32(float x) {
    unsigned u;
    asm volatile("cvt.rna.tf32.f32 %0, %1;" : "=r"(u) : "f"(x));
    return __uint_as_float(u);
}

__device__ __forceinline__ void mma_tf32(float c[4], const unsigned a[4],
                                         unsigned b0, unsigned b1) {
    asm volatile(
        "mma.sync.aligned.m16n8k8.row.col.f32.tf32.tf32.f32 "
        "{%0,%1,%2,%3}, {%4,%5,%6,%7}, {%8,%9}, {%0,%1,%2,%3};\n"
        : "+f"(c[0]), "+f"(c[1]), "+f"(c[2]), "+f"(c[3])
        : "r"(a[0]), "r"(a[1]), "r"(a[2]), "r"(a[3]), "r"(b0), "r"(b1));
}

// ---------------------------------------------------------------------------
// Prep 1: weight transpose w[d][c][k] -> g_w2[k][d][c] (pre-rounded to tf32)
// ---------------------------------------------------------------------------
__global__ void prep_weight(const float* __restrict__ w) {
    int i = blockIdx.x * blockDim.x + threadIdx.x;
    const int total = KT * COUT * CIN;
    if (i >= total) return;
    int c = i & (CIN - 1);
    int d = (i >> 9) & (COUT - 1);
    int k = i / (COUT * CIN);
    float v = w[((size_t)d * CIN + c) * KT + k];
    g_w2[i] = to_tf32(v);
}

// ---------------------------------------------------------------------------
// Prep 2: gather params per (b, o, k): j0 = u0 - o in [0,6], g0, g1.
// Replicates the reference fp32 arithmetic exactly. Padded o in [OUTL,4096)
// gets zeros.
// ---------------------------------------------------------------------------
__global__ void prep_gather(const float* __restrict__ off) {
    int i = blockIdx.x * blockDim.x + threadIdx.x;
    const int total = BATCH * 4096 * KT;
    if (i >= total) return;
    int k = i % KT;
    int o = (i / KT) & 4095;
    int b = i / (KT * 4096);
    float gg0 = 0.f, gg1 = 0.f;
    int j0 = 0;
    if (o < OUTL) {
        float T = (float)(o + k) + off[((size_t)b * OUTL + o) * KT + k];
        T = fmaxf(T, (float)o);
        T = fminf(T, (float)(o + (KT - 1)));
        int U0 = (int)floorf(T);
        if (U0 < 0) U0 = 0;
        if (U0 > LIN - 2) U0 = LIN - 2;
        gg0 = fmaxf(0.f, 1.f - fabsf((float)U0 - T));
        gg1 = fmaxf(0.f, 1.f - fabsf((float)(U0 + 1) - T));
        j0 = U0 - o;
    }
    g_j0[i] = j0;
    g_g0[i] = gg0;
    g_g1[i] = gg1;
}

// ---------------------------------------------------------------------------
// Main fused gather + GEMM kernel.
// CTA: 128 (d) x 128 (o) output tile for one batch.
// Reduction: 16 c-chunks of 32, each reused across 7 kernel taps.
// Per (chunk, tap): stage W2 tile + build samp tile in SMEM, then 4x tf32 mma
// k8-steps per warp (8 warps in 4x2 layout, warp tile 32x64).
// ---------------------------------------------------------------------------
__global__ __launch_bounds__(256)
void deform_main(const float* __restrict__ x, const float* __restrict__ bias,
                 float* __restrict__ out) {
    extern __shared__ float smf[];
    float*  xs  = smf;                            // 32*136
    float*  ws  = xs + BK * TW;                   // 128*36
    float*  sp  = ws + BM * WS_STRIDE;            // 32*132
    float2* g01 = (float2*)(sp + BK * SP_STRIDE); // 7*128
    int*    jsm = (int*)(g01 + KT * BN);          // 7*128

    const int tid = threadIdx.x;
    const int o0 = blockIdx.x * BN;
    const int d0 = blockIdx.y * BM;
    const int b  = blockIdx.z;

    // Stage gather params for this o-tile (all taps)
    for (int i = tid; i < KT * BN; i += 256) {
        int k = i / BN, o = i - k * BN;
        int gi = ((b * 4096) + o0 + o) * KT + k;
        jsm[i] = g_j0[gi];
        g01[i] = make_float2(g_g0[gi], g_g1[gi]);
    }

    const int lane = tid & 31;
    const int wid  = tid >> 5;
    const int wm = wid & 3, wn = wid >> 2;
    const int m_base = wm * 32, n_base = wn * 64;
    const int qg = lane >> 2, tq = lane & 3;

    float acc[2][8][4];
#pragma unroll
    for (int mi = 0; mi < 2; ++mi)
#pragma unroll
        for (int ni = 0; ni < 8; ++ni)
#pragma unroll
            for (int q = 0; q < 4; ++q) acc[mi][ni][q] = 0.f;

    for (int c0 = 0; c0 < CIN; c0 += BK) {
        __syncthreads();   // previous consumers done before overwriting xs
        // Stage x window [c0..c0+31] x [o0..o0+135]
        for (int i = tid; i < BK * TW; i += 256) {
            int c = i / TW, t = i - c * TW;
            int gt = o0 + t;
            xs[i] = (gt < LIN) ? x[((size_t)(b * CIN + c0 + c)) * LIN + gt] : 0.f;
        }

        for (int k = 0; k < KT; ++k) {
            __syncthreads();   // xs ready / previous tap's mma done
            // Stage W2 tile for tap k: [d0..d0+127] x [c0..c0+31]
            {
                int r0 = tid >> 3;
                int cq = (tid & 7) * 4;
#pragma unroll
                for (int rr = r0; rr < BM; rr += 32) {
                    float4 v = *reinterpret_cast<const float4*>(
                        &g_w2[((size_t)(k * COUT + d0 + rr)) * CIN + c0 + cq]);
                    float* wp = &ws[rr * WS_STRIDE + cq];
                    wp[0] = v.x; wp[1] = v.y; wp[2] = v.z; wp[3] = v.w;
                }
            }
            // Build samp tile for tap k: sp[c][o] = g0*x[o+j0] + g1*x[o+j0+1]
            {
                int o  = tid & 127;
                int ch = tid >> 7;  // 0..1
                int j  = jsm[k * BN + o];
                float2 gg = g01[k * BN + o];
                int base = o + j;
#pragma unroll
                for (int c = ch; c < BK; c += 2) {
                    float v = gg.x * xs[c * TW + base] + gg.y * xs[c * TW + base + 1];
                    sp[c * SP_STRIDE + o] = to_tf32(v);
                }
            }
            __syncthreads();
            // 4 x k8 mma steps
#pragma unroll
            for (int kk = 0; kk < 4; ++kk) {
                unsigned a[2][4];
#pragma unroll
                for (int mi = 0; mi < 2; ++mi) {
                    const float* wp = &ws[(m_base + mi * 16 + qg) * WS_STRIDE + kk * 8 + tq];
                    a[mi][0] = __float_as_uint(wp[0]);
                    a[mi][1] = __float_as_uint(wp[8 * WS_STRIDE]);
                    a[mi][2] = __float_as_uint(wp[4]);
                    a[mi][3] = __float_as_uint(wp[8 * WS_STRIDE + 4]);
                }
#pragma unroll
                for (int ni = 0; ni < 8; ++ni) {
                    const float* bp = &sp[(kk * 8 + tq) * SP_STRIDE + n_base + ni * 8 + qg];
                    unsigned b0 = __float_as_uint(bp[0]);
                    unsigned b1 = __float_as_uint(bp[4 * SP_STRIDE]);
                    mma_tf32(acc[0][ni], a[0], b0, b1);
                    mma_tf32(acc[1][ni], a[1], b0, b1);
                }
            }
        }
    }

    // Epilogue: add bias, store (guard o < OUTL)
#pragma unroll
    for (int mi = 0; mi < 2; ++mi) {
        int row = d0 + m_base + mi * 16 + qg;
        float bz0 = bias[row];
        float bz1 = bias[row + 8];
#pragma unroll
        for (int ni = 0; ni < 8; ++ni) {
            int col = o0 + n_base + ni * 8 + 2 * tq;
            size_t base = ((size_t)b * COUT + row) * OUTL + col;
            if (col < OUTL) {
                out[base] = acc[mi][ni][0] + bz0;
                out[base + (size_t)8 * OUTL] = acc[mi][ni][2] + bz1;
                if (col + 1 < OUTL) {
                    out[base + 1] = acc[mi][ni][1] + bz0;
                    out[base + (size_t)8 * OUTL + 1] = acc[mi][ni][3] + bz1;
                }
            }
        }
    }
}

// ---------------------------------------------------------------------------
extern "C" void kernel_launch(void* const* d_in, const int* in_sizes, int n_in,
                              void* d_out, int out_size) {
    const float* x    = (const float*)d_in[0];
    const float* off  = (const float*)d_in[1];
    const float* w    = (const float*)d_in[2];
    const float* bias = (const float*)d_in[3];
    float* out = (float*)d_out;

    {
        int total = KT * COUT * CIN;
        prep_weight<<<(total + 255) / 256, 256>>>(w);
    }
    {
        int total = BATCH * 4096 * KT;
        prep_gather<<<(total + 255) / 256, 256>>>(off);
    }

    int smem_bytes = (BK * TW + BM * WS_STRIDE + BK * SP_STRIDE) * 4
                   + KT * BN * 8 + KT * BN * 4;   // 63488
    cudaFuncSetAttribute(deform_main, cudaFuncAttributeMaxDynamicSharedMemorySize,
                         smem_bytes);
    dim3 grid((OUTL + BN - 1) / BN, COUT / BM, BATCH);
    deform_main<<<grid, 256, smem_bytes>>>(x, bias, out);
}

// round 7
// speedup vs baseline: 2.2403x; 2.2403x over previous
#include <cuda_runtime.h>
#include <cuda_fp16.h>
#include <cstdint>

// ---------------------------------------------------------------------------
// Problem constants
// ---------------------------------------------------------------------------
#define CIN     512
#define COUT    512
#define LIN     4096
#define KT      7
#define OUTL    4090
#define BATCH   4

// Tiling: CTA = 256 (d) x 128 (o), K-chunk 32 c per step, 112 steps total.
#define BM      256
#define BN      128
#define BK      32
#define NSTEPS  (CIN / BK * KT)   // 112
#define THREADS 512

// SMEM layout (bytes). A: 3 stages x 256 rows x 80B. B: 2 stages x 128 x 80B.
// xs: 2 stages x 32 rows x 144 floats. Row stride 80B => (5*r mod 8) bank map,
// conflict-free ldmatrix.
#define AROW    80
#define ASTG    (BM * AROW)        // 20480
#define BSTG    (BN * AROW)        // 10240
#define XROWF   144                // floats per xs row (576B, 16B-aligned)
#define XSTG    (BK * XROWF * 4)   // 18432

#define A_OFF   0                  // 3 * ASTG = 61440
#define B_OFF   61440              // 2 * BSTG = 20480
#define XS_OFF  81920              // 2 * XSTG = 36864
#define G01_OFF 118784             // 7*128*8 = 7168
#define JSM_OFF 125952             // 7*128*4 = 3584
#define SMEM_TOTAL 129536

// ---------------------------------------------------------------------------
// Scratch (no allocations allowed -> __device__ globals)
// ---------------------------------------------------------------------------
__device__ __half g_wh[(size_t)KT * COUT * CIN];   // [k][d][c] fp16
__device__ float  g_g0[(size_t)BATCH * 4096 * KT];
__device__ float  g_g1[(size_t)BATCH * 4096 * KT];
__device__ int    g_j0[(size_t)BATCH * 4096 * KT];

// ---------------------------------------------------------------------------
// Helpers
// ---------------------------------------------------------------------------
__device__ __forceinline__ uint32_t smem_u32(const void* p) {
    uint32_t a;
    asm("{ .reg .u64 t; cvta.to.shared.u64 t, %1; cvt.u32.u64 %0, t; }" : "=r"(a) : "l"(p));
    return a;
}
__device__ __forceinline__ void cp16(uint32_t dst, const void* src) {
    asm volatile("cp.async.cg.shared.global [%0], [%1], 16;" :: "r"(dst), "l"(src));
}
__device__ __forceinline__ void cp16z(uint32_t dst, const void* src, int nbytes) {
    asm volatile("cp.async.cg.shared.global [%0], [%1], 16, %2;"
                 :: "r"(dst), "l"(src), "r"(nbytes));
}
#define CP_COMMIT() asm volatile("cp.async.commit_group;" ::: "memory")
#define CP_WAIT(N)  asm volatile("cp.async.wait_group %0;" :: "n"(N) : "memory")

__device__ __forceinline__ void ldsm4(uint32_t& r0, uint32_t& r1, uint32_t& r2,
                                      uint32_t& r3, uint32_t addr) {
    asm volatile("ldmatrix.sync.aligned.m8n8.x4.shared.b16 {%0,%1,%2,%3}, [%4];"
                 : "=r"(r0), "=r"(r1), "=r"(r2), "=r"(r3) : "r"(addr));
}
__device__ __forceinline__ void mma_f16(float c[4], const uint32_t a[4],
                                        uint32_t b0, uint32_t b1) {
    asm volatile(
        "mma.sync.aligned.m16n8k16.row.col.f32.f16.f16.f32 "
        "{%0,%1,%2,%3}, {%4,%5,%6,%7}, {%8,%9}, {%0,%1,%2,%3};\n"
        : "+f"(c[0]), "+f"(c[1]), "+f"(c[2]), "+f"(c[3])
        : "r"(a[0]), "r"(a[1]), "r"(a[2]), "r"(a[3]), "r"(b0), "r"(b1));
}

// ---------------------------------------------------------------------------
// Prep 1: weight transpose w[d][c][k] -> g_wh[k][d][c] fp16
// ---------------------------------------------------------------------------
__global__ void prep_weight(const float* __restrict__ w) {
    int i = blockIdx.x * blockDim.x + threadIdx.x;
    const int total = KT * COUT * CIN;
    if (i >= total) return;
    int c = i & (CIN - 1);
    int d = (i >> 9) & (COUT - 1);
    int k = i / (COUT * CIN);
    g_wh[i] = __float2half(w[((size_t)d * CIN + c) * KT + k]);
}

// ---------------------------------------------------------------------------
// Prep 2: gather params per (b, o, k). Padded o in [OUTL,4096) -> zeros.
// ---------------------------------------------------------------------------
__global__ void prep_gather(const float* __restrict__ off) {
    int i = blockIdx.x * blockDim.x + threadIdx.x;
    const int total = BATCH * 4096 * KT;
    if (i >= total) return;
    int k = i % KT;
    int o = (i / KT) & 4095;
    int b = i / (KT * 4096);
    float gg0 = 0.f, gg1 = 0.f;
    int j0 = 0;
    if (o < OUTL) {
        float T = (float)(o + k) + off[((size_t)b * OUTL + o) * KT + k];
        T = fmaxf(T, (float)o);
        T = fminf(T, (float)(o + (KT - 1)));
        int U0 = (int)floorf(T);
        if (U0 < 0) U0 = 0;
        if (U0 > LIN - 2) U0 = LIN - 2;
        gg0 = fmaxf(0.f, 1.f - fabsf((float)U0 - T));
        gg1 = fmaxf(0.f, 1.f - fabsf((float)(U0 + 1) - T));
        j0 = U0 - o;
    }
    g_j0[i] = j0;
    g_g0[i] = gg0;
    g_g1[i] = gg1;
}

// ---------------------------------------------------------------------------
// Main: fp16 mma.sync m16n8k16 fused gather-GEMM.
// 16 warps: wm = wid&7 (m 32 each), wn = wid>>3 (n 64 each).
// Pipeline: A triple-buffered cp.async (dist 2); xs double-buffered cp.async
// (issued at k==4, consumed 2 steps later); B (samp) double-buffered, built in
// SMEM by all threads each step for step s+1.
// ---------------------------------------------------------------------------
__global__ __launch_bounds__(THREADS)
void deform_mma(const float* __restrict__ x, const float* __restrict__ bias,
                float* __restrict__ out) {
    extern __shared__ char smem[];
    const uint32_t sbase = smem_u32(smem);
    float2* g01 = (float2*)(smem + G01_OFF);
    int*    jsm = (int*)(smem + JSM_OFF);

    const int tid  = threadIdx.x;
    const int lane = tid & 31;
    const int wid  = tid >> 5;
    const int o0 = blockIdx.x * BN;
    const int d0 = blockIdx.y * BM;
    const int b  = blockIdx.z;

    const int m_base = (wid & 7) * 32;
    const int n_base = (wid >> 3) * 64;

    // ---- stage gather params for this o-tile ----
    for (int i = tid; i < KT * BN; i += THREADS) {
        int k = i >> 7, o = i & 127;
        int gi = ((b * 4096) + o0 + o) * KT + k;
        jsm[i] = g_j0[gi];
        g01[i] = make_float2(g_g0[gi], g_g1[gi]);
    }

    // ---- prologue: A[0]->buf0, A[1]->buf1, xs chunk0 ----
    {
#pragma unroll
        for (int st = 0; st < 2; ++st) {
            const __half* wsrc = g_wh + ((size_t)st * COUT + d0) * CIN;  // k=st, c0=0
            uint32_t dbase = sbase + A_OFF + st * ASTG;
#pragma unroll
            for (int it = 0; it < 2; ++it) {
                int i = tid + it * THREADS;
                int r = i >> 2, ch = i & 3;
                cp16(dbase + r * AROW + ch * 16, wsrc + (size_t)r * CIN + ch * 8);
            }
        }
        uint32_t dxb = sbase + XS_OFF;     // chunk 0 -> xs buf 0
        for (int i = tid; i < 1088; i += THREADS) {
            int r = i / 34, q = i - r * 34;
            int gt0 = o0 + q * 4;
            const float* src = x + ((size_t)(b * CIN + r)) * LIN + gt0;
            int rem = LIN - gt0;
            int nv = rem >= 4 ? 16 : (rem > 0 ? rem * 4 : 0);
            if (nv == 0) src = x;
            cp16z(dxb + r * 576 + q * 16, src, nv);
        }
        CP_COMMIT();
        CP_WAIT(0);
        __syncthreads();
        // build B[0] (k=0, chunk 0) into B buf 0
        const float* xsf = (const float*)(smem + XS_OFF);
        int o = tid & 127, cb = tid >> 7;
        int j = jsm[o];
        float2 g = g01[o];
        int base = cb * 8 * XROWF + o + j;
        __half2 h[4];
#pragma unroll
        for (int i2 = 0; i2 < 4; ++i2) {
            float v0 = g.x * xsf[base + (2 * i2) * XROWF]     + g.y * xsf[base + (2 * i2) * XROWF + 1];
            float v1 = g.x * xsf[base + (2 * i2 + 1) * XROWF] + g.y * xsf[base + (2 * i2 + 1) * XROWF + 1];
            h[i2] = __floats2half2_rn(v0, v1);
        }
        *reinterpret_cast<uint4*>(smem + B_OFF + o * AROW + cb * 16)
            = *reinterpret_cast<uint4*>(h);
        __syncthreads();
    }

    float acc[2][8][4];
#pragma unroll
    for (int mi = 0; mi < 2; ++mi)
#pragma unroll
        for (int ni = 0; ni < 8; ++ni)
#pragma unroll
            for (int q = 0; q < 4; ++q) acc[mi][ni][q] = 0.f;

    // ---- mainloop ----
    for (int cc = 0; cc < 16; ++cc) {
#pragma unroll
        for (int k = 0; k < KT; ++k) {
            const int s = cc * KT + k;
            // issue A for step s+2 (wraps harmlessly at the tail)
            {
                int k2 = k + 2, cc2 = cc;
                if (k2 >= KT) { k2 -= KT; cc2 += 1; }
                if (cc2 >= 16) { cc2 = 0; k2 = 0; }
                const int buf = (s + 2) % 3;
                const __half* wsrc = g_wh + ((size_t)k2 * COUT + d0) * CIN + cc2 * BK;
                uint32_t dbase = sbase + A_OFF + buf * ASTG;
#pragma unroll
                for (int it = 0; it < 2; ++it) {
                    int i = tid + it * THREADS;
                    int r = i >> 2, ch = i & 3;
                    cp16(dbase + r * AROW + ch * 16, wsrc + (size_t)r * CIN + ch * 8);
                }
            }
            // issue xs for chunk cc+1 two steps before it is consumed
            if (k == 4 && cc + 1 < 16) {
                const int cn = cc + 1;
                uint32_t dxb = sbase + XS_OFF + (cn & 1) * XSTG;
                for (int i = tid; i < 1088; i += THREADS) {
                    int r = i / 34, q = i - r * 34;
                    int gt0 = o0 + q * 4;
                    const float* src = x + ((size_t)(b * CIN + cn * BK + r)) * LIN + gt0;
                    int rem = LIN - gt0;
                    int nv = rem >= 4 ? 16 : (rem > 0 ? rem * 4 : 0);
                    if (nv == 0) src = x;
                    cp16z(dxb + r * 576 + q * 16, src, nv);
                }
            }
            CP_COMMIT();
            CP_WAIT(2);        // 3 groups pending after commit -> forces A[s] (+xs)
            __syncthreads();

            // ---- mma for step s ----
            {
                uint32_t abase = sbase + A_OFF + (s % 3) * ASTG;
                uint32_t bbase = sbase + B_OFF + (s & 1) * BSTG;
#pragma unroll
                for (int kk = 0; kk < 2; ++kk) {
                    uint32_t afr[2][4];
#pragma unroll
                    for (int mi = 0; mi < 2; ++mi) {
                        uint32_t addr = abase
                            + (uint32_t)(m_base + mi * 16 + (lane & 15)) * AROW
                            + kk * 32 + (lane & 16);
                        ldsm4(afr[mi][0], afr[mi][1], afr[mi][2], afr[mi][3], addr);
                    }
                    uint32_t bfr[8][2];
#pragma unroll
                    for (int nb = 0; nb < 4; ++nb) {
                        uint32_t addr = bbase
                            + (uint32_t)(n_base + nb * 16 + (lane & 7) + ((lane & 16) >> 1)) * AROW
                            + kk * 32 + ((lane & 8) << 1);
                        ldsm4(bfr[2 * nb][0], bfr[2 * nb][1],
                              bfr[2 * nb + 1][0], bfr[2 * nb + 1][1], addr);
                    }
#pragma unroll
                    for (int ni = 0; ni < 8; ++ni) {
                        mma_f16(acc[0][ni], afr[0], bfr[ni][0], bfr[ni][1]);
                        mma_f16(acc[1][ni], afr[1], bfr[ni][0], bfr[ni][1]);
                    }
                }
            }

            // ---- build B[s+1] into the other B buffer ----
            if (s + 1 < NSTEPS) {
                const int kn = (k + 1 < KT) ? k + 1 : 0;
                const int cn = (k + 1 < KT) ? cc : cc + 1;
                const float* xsf = (const float*)(smem + XS_OFF + (cn & 1) * XSTG);
                int o = tid & 127, cb = tid >> 7;
                int j = jsm[kn * BN + o];
                float2 g = g01[kn * BN + o];
                int base = cb * 8 * XROWF + o + j;
                __half2 h[4];
#pragma unroll
                for (int i2 = 0; i2 < 4; ++i2) {
                    float v0 = g.x * xsf[base + (2 * i2) * XROWF]
                             + g.y * xsf[base + (2 * i2) * XROWF + 1];
                    float v1 = g.x * xsf[base + (2 * i2 + 1) * XROWF]
                             + g.y * xsf[base + (2 * i2 + 1) * XROWF + 1];
                    h[i2] = __floats2half2_rn(v0, v1);
                }
                *reinterpret_cast<uint4*>(smem + B_OFF + ((s + 1) & 1) * BSTG
                                          + o * AROW + cb * 16)
                    = *reinterpret_cast<uint4*>(h);
            }
            __syncthreads();
        }
    }

    // ---- epilogue: bias add + store ----
    const int qg = lane >> 2, tq = lane & 3;
#pragma unroll
    for (int mi = 0; mi < 2; ++mi) {
        int d = d0 + m_base + mi * 16 + qg;
        float bz0 = bias[d];
        float bz1 = bias[d + 8];
        size_t row0 = ((size_t)b * COUT + d) * OUTL;
        size_t row1 = row0 + (size_t)8 * OUTL;
#pragma unroll
        for (int ni = 0; ni < 8; ++ni) {
            int col = o0 + n_base + ni * 8 + 2 * tq;
            if (col < OUTL) {   // col even, OUTL even => col+1 < OUTL too
                float2 v0 = make_float2(acc[mi][ni][0] + bz0, acc[mi][ni][1] + bz0);
                float2 v1 = make_float2(acc[mi][ni][2] + bz1, acc[mi][ni][3] + bz1);
                *reinterpret_cast<float2*>(out + row0 + col) = v0;
                *reinterpret_cast<float2*>(out + row1 + col) = v1;
            }
        }
    }
}

// ---------------------------------------------------------------------------
extern "C" void kernel_launch(void* const* d_in, const int* in_sizes, int n_in,
                              void* d_out, int out_size) {
    const float* x    = (const float*)d_in[0];
    const float* off  = (const float*)d_in[1];
    const float* w    = (const float*)d_in[2];
    const float* bias = (const float*)d_in[3];
    float* out = (float*)d_out;

    {
        int total = KT * COUT * CIN;
        prep_weight<<<(total + 255) / 256, 256>>>(w);
    }
    {
        int total = BATCH * 4096 * KT;
        prep_gather<<<(total + 255) / 256, 256>>>(off);
    }

    cudaFuncSetAttribute(deform_mma, cudaFuncAttributeMaxDynamicSharedMemorySize,
                         SMEM_TOTAL);
    dim3 grid(4096 / BN, COUT / BM, BATCH);   // 32 x 2 x 4 = 256 CTAs
    deform_mma<<<grid, THREADS, SMEM_TOTAL>>>(x, bias, out);
}